// round 5
// baseline (speedup 1.0000x reference)
#include <cuda_runtime.h>
#include <math.h>

#define EMB 256
#define NH1 32
#define NH2 16
#define MAXDAGS 1024
#define MAXOPS  102400

// ---------------- scratch (device globals; no allocation allowed) ----------------
__device__ int   g_offsets[MAXDAGS + 1];
__device__ int   g_dagid[MAXOPS];
__device__ float g_yzop[MAXDAGS * NH1];
__device__ float g_prpre[MAXDAGS * NH1];
__device__ float g_zop[NH1];
__device__ float g_zpr[NH1];
__device__ float g_partial[1024];
__device__ float g_inv;
__device__ unsigned int g_counter;

// ---------------- f32x2 helpers ----------------
__device__ __forceinline__ void ffma2(unsigned long long& d, unsigned long long a, unsigned long long b) {
    asm("fma.rn.f32x2 %0, %1, %2, %0;" : "+l"(d) : "l"(a), "l"(b));
}
__device__ __forceinline__ unsigned long long pack2(float x, float y) {
    unsigned long long r;
    asm("mov.b64 %0, {%1,%2};" : "=l"(r) : "f"(x), "f"(y));
    return r;
}
__device__ __forceinline__ float2 unpack2(unsigned long long v) {
    float2 r;
    asm("mov.b64 {%0,%1}, %2;" : "=f"(r.x), "=f"(r.y) : "l"(v));
    return r;
}

// ================= kernel A: block0 = prefix scan (+counter reset), block1 = z-dots =================
__global__ void __launch_bounds__(1024) k_A(
    const int* __restrict__ num_ops, const float* __restrict__ z,
    const float* __restrict__ opW1, const float* __restrict__ opb1,
    const float* __restrict__ prW1, const float* __restrict__ prb1, int D)
{
    __shared__ int s[1024];
    __shared__ float sz[EMB];
    int t = threadIdx.x;
    if (blockIdx.x == 0) {
        if (t == 0) g_counter = 0u;
        int v = (t < D) ? num_ops[t] : 0;
        s[t] = v;
        __syncthreads();
        for (int off = 1; off < 1024; off <<= 1) {
            int u = (t >= off) ? s[t - off] : 0;
            __syncthreads();
            s[t] += u;
            __syncthreads();
        }
        g_offsets[t + 1] = s[t];
        if (t == 0) g_offsets[0] = 0;
    } else {
        for (int i = t; i < EMB; i += 1024) sz[i] = z[i];
        __syncthreads();
        if (t < 64) {
            int j = t & 31;
            const float* W = (t < 32) ? (opW1 + 2 * EMB * NH1) : (prW1 + (1 + EMB) * NH1);
            float a0 = 0.f, a1 = 0.f, a2 = 0.f, a3 = 0.f;
            for (int k = 0; k < EMB; k += 4) {
                a0 += sz[k + 0] * W[(k + 0) * NH1 + j];
                a1 += sz[k + 1] * W[(k + 1) * NH1 + j];
                a2 += sz[k + 2] * W[(k + 2) * NH1 + j];
                a3 += sz[k + 3] * W[(k + 3) * NH1 + j];
            }
            float a = (a0 + a1) + (a2 + a3);
            if (t < 32) g_zop[j] = a + opb1[j];
            else        g_zpr[j] = a + prb1[j];
        }
    }
}

// ================= kernel B: blocks [0,nbF) = binary-search dag-id fill; rest = per-dag y-dots =================
__global__ void __launch_bounds__(512) k_B(
    const float* __restrict__ y,
    const float* __restrict__ opW1, const float* __restrict__ prW1,
    int D, int N, int nbF, int nb16)
{
    __shared__ float sy[16 * EMB];   // 16 KB (also aliases offsets for fill blocks)
    __shared__ float sw[64 * NH1];   // 8 KB
    int t = threadIdx.x;

    if ((int)blockIdx.x < nbF) {
        int* soff = reinterpret_cast<int*>(sy);
        for (int i = t; i <= D; i += 512) soff[i] = g_offsets[i];
        __syncthreads();
        int i = blockIdx.x * 512 + t;
        if (i < N) {
            int lo = 0, hi = D;
            while (lo < hi) {
                int mid = (lo + hi) >> 1;
                if (soff[mid + 1] <= i) lo = mid + 1; else hi = mid;
            }
            if (lo >= D) lo = D - 1;
            g_dagid[i] = lo;
        }
        return;
    }
    int bp = blockIdx.x - nbF;
    int branch = (bp >= nb16) ? 1 : 0;
    int chunk = branch ? bp - nb16 : bp;
    int w = t >> 5, j = t & 31;
    int d = chunk * 16 + w;

    for (int idx = t; idx < 16 * EMB; idx += 512) {
        int dd = chunk * 16 + (idx >> 8);
        sy[idx] = (dd < D) ? y[(size_t)dd * EMB + (idx & 255)] : 0.f;
    }
    const float* Wm = branch ? (prW1 + NH1) : (opW1 + EMB * NH1);
    float a0 = 0.f, a1 = 0.f;
    for (int kc = 0; kc < EMB; kc += 64) {
        __syncthreads();
        for (int idx = t; idx < 64 * NH1; idx += 512) sw[idx] = Wm[(size_t)kc * NH1 + idx];
        __syncthreads();
        const float* yr = sy + w * EMB + kc;
#pragma unroll
        for (int k = 0; k < 64; k += 2) {
            a0 += yr[k + 0] * sw[(k + 0) * NH1 + j];
            a1 += yr[k + 1] * sw[(k + 1) * NH1 + j];
        }
    }
    if (d < D) {
        float a = a0 + a1;
        if (!branch) g_yzop[d * NH1 + j]  = a + g_zop[j];
        else         g_prpre[d * NH1 + j] = a + g_zpr[j];
    }
}

// ================= kernel C (fused): blocks [0,nbPR) = prlvl branch; rest = main GEMM =================
#define BM 128
#define KC 64
#define SXP 66    // x tile row stride (floats, even for LDS.64 / STS.64)
#define SHP 34    // h-pre row stride

__global__ void __launch_bounds__(256, 3) k_ops(
    const float* __restrict__ x,  const float* __restrict__ W1,
    const float* __restrict__ W2, const float* __restrict__ b2,
    const float* __restrict__ W3, const float* __restrict__ b3,
    const float* __restrict__ msk,
    const float* __restrict__ prW1, const float* __restrict__ prW2,
    const float* __restrict__ prb2, const float* __restrict__ prW3,
    const float* __restrict__ prb3, const float* __restrict__ pmsk,
    float* __restrict__ out, float* __restrict__ outp,
    int N, int W, int D, int nbPR, int nb)
{
    // phase1: x tile row-major [BM][SXP] (33.8 KB); phase2 alias: h-pre [BM][SHP]
    __shared__ float s_buf[BM * SXP];
    __shared__ float swi[(KC / 2) * 64];   // interleaved W1 chunk: [kp][2j+e]  (8 KB)
    __shared__ float sw2[NH1 * NH2];
    __shared__ float sb2[NH2], sw3[NH2];
    __shared__ float sb3v;
    __shared__ float swr[8];
    __shared__ int   s_last;

    int tid  = threadIdx.x;
    int w    = tid >> 5;
    int lane = tid & 31;

    // ---------------- prlvl path: 4 dags per block ----------------
    if ((int)blockIdx.x < nbPR) {
        float* spre = s_buf;               // 128 floats
        float* sr0  = s_buf + 128;         // 32
        float* sW2p = sw2;
        int dbase = blockIdx.x * 4;
        int dl = tid >> 6, wk = tid & 63;
        int d = dbase + dl;

        if (tid < 4 * NH1) {
            int dd = dbase + (tid >> 5);
            spre[tid] = (dd < D) ? g_prpre[dbase * NH1 + tid] : 0.f;
        }
        if (tid >= 128 && tid < 160) sr0[tid - 128] = prW1[tid - 128];
        for (int i = tid; i < NH1 * NH2; i += 256) sW2p[i] = prW2[i];
        if (tid >= 160 && tid < 176) { sb2[tid - 160] = prb2[tid - 160]; sw3[tid - 160] = prW3[tid - 160]; }
        if (tid == 176) sb3v = prb3[0];
        __syncthreads();

        const unsigned long long* w2p = reinterpret_cast<const unsigned long long*>(sW2p);
        float l = -1e30f;
        if (d < D && wk < W) {
            float lim = (float)(wk + 1);
            float h1[NH1];
#pragma unroll
            for (int j = 0; j < NH1; j++) h1[j] = fmaxf(spre[dl * NH1 + j] + lim * sr0[j], 0.f);
            unsigned long long a2[8];
#pragma unroll
            for (int p = 0; p < 8; p++) a2[p] = pack2(sb2[2 * p], sb2[2 * p + 1]);
#pragma unroll
            for (int j = 0; j < NH1; j++) {
                unsigned long long hd = pack2(h1[j], h1[j]);
#pragma unroll
                for (int p = 0; p < 8; p++) ffma2(a2[p], hd, w2p[j * 8 + p]);
            }
            float logit = sb3v;
#pragma unroll
            for (int p = 0; p < 8; p++) {
                float2 f = unpack2(a2[p]);
                logit += fmaxf(f.x, 0.f) * sw3[2 * p] + fmaxf(f.y, 0.f) * sw3[2 * p + 1];
            }
            l = logit - (1.f - pmsk[(size_t)d * W + wk]) * 1000.f;
        }
        float m = l;
#pragma unroll
        for (int off = 16; off; off >>= 1) m = fmaxf(m, __shfl_xor_sync(0xffffffffu, m, off));
        if (lane == 0) swr[w] = m;
        __syncthreads();
        m = fmaxf(swr[dl * 2], swr[dl * 2 + 1]);
        float e = (d < D && wk < W) ? expf(l - m) : 0.f;
        float s = e;
#pragma unroll
        for (int off = 16; off; off >>= 1) s += __shfl_xor_sync(0xffffffffu, s, off);
        __syncthreads();
        if (lane == 0) swr[w] = s;
        __syncthreads();
        s = swr[dl * 2] + swr[dl * 2 + 1];
        if (d < D && wk < W) outp[(size_t)d * W + wk] = e / s;
        return;
    }

    // ---------------- GEMM path ----------------
    int blk  = blockIdx.x - nbPR;
    int bm   = blk * BM;
    int j0   = (w & 3) * 8;              // warp -> 8 j's (broadcast within warp)
    int rh   = (w >> 2) * 64;            // row half

    if (tid < 16) { sb2[tid] = b2[tid]; sw3[tid] = W3[tid]; }
    if (tid == 16) sb3v = b3[0];
    for (int i = tid; i < NH1 * NH2; i += 256) sw2[i] = W2[i];

    unsigned long long acc[2][8];
#pragma unroll
    for (int i = 0; i < 2; i++)
#pragma unroll
        for (int p = 0; p < 8; p++) acc[i][p] = 0ull;

    for (int kc = 0; kc < EMB; kc += KC) {
        __syncthreads();
        // stage x tile row-major via float2 (coalesced LDG.64, aligned STS.64)
#pragma unroll
        for (int it = 0; it < 16; it++) {
            int fi = it * 256 + tid;
            int row = fi >> 5, c2 = fi & 31;
            int n = bm + row;
            float2 v = make_float2(0.f, 0.f);
            if (n < N) v = *reinterpret_cast<const float2*>(&x[(size_t)n * EMB + kc + c2 * 2]);
            *reinterpret_cast<float2*>(&s_buf[row * SXP + c2 * 2]) = v;
        }
        // stage W1 chunk interleaved: swi[kp*64 + r] = W1[(kc+2kp+(r&1))*32 + (r>>1)]
#pragma unroll
        for (int it = 0; it < 8; it++) {
            int idx = it * 256 + tid;            // 0..2047
            int kp = idx >> 6, r = idx & 63;
            swi[kp * 64 + r] = W1[(size_t)(kc + 2 * kp + (r & 1)) * NH1 + (r >> 1)];
        }
        __syncthreads();
#pragma unroll 4
        for (int kp = 0; kp < KC / 2; kp++) {
            unsigned long long xk0 = *reinterpret_cast<const unsigned long long*>(
                &s_buf[(rh + lane) * SXP + 2 * kp]);
            unsigned long long xk1 = *reinterpret_cast<const unsigned long long*>(
                &s_buf[(rh + lane + 32) * SXP + 2 * kp]);
            const ulonglong2* wp = reinterpret_cast<const ulonglong2*>(&swi[kp * 64 + 2 * j0]);
            ulonglong2 wa = wp[0], wb = wp[1], wc = wp[2], wd = wp[3];
            ffma2(acc[0][0], xk0, wa.x); ffma2(acc[0][1], xk0, wa.y);
            ffma2(acc[0][2], xk0, wb.x); ffma2(acc[0][3], xk0, wb.y);
            ffma2(acc[0][4], xk0, wc.x); ffma2(acc[0][5], xk0, wc.y);
            ffma2(acc[0][6], xk0, wd.x); ffma2(acc[0][7], xk0, wd.y);
            ffma2(acc[1][0], xk1, wa.x); ffma2(acc[1][1], xk1, wa.y);
            ffma2(acc[1][2], xk1, wb.x); ffma2(acc[1][3], xk1, wb.y);
            ffma2(acc[1][4], xk1, wc.x); ffma2(acc[1][5], xk1, wc.y);
            ffma2(acc[1][6], xk1, wd.x); ffma2(acc[1][7], xk1, wd.y);
        }
    }
    __syncthreads();
    // reduce lanes (even+odd k) and stage h-pre
#pragma unroll
    for (int i = 0; i < 2; i++) {
        int row = rh + lane + 32 * i;
#pragma unroll
        for (int p = 0; p < 8; p++) {
            float2 f = unpack2(acc[i][p]);
            s_buf[row * SHP + j0 + p] = f.x + f.y;
        }
    }
    __syncthreads();

    // ---- tail: rows 0..127 handled by tid<128 ----
    const unsigned long long* w2_64 = reinterpret_cast<const unsigned long long*>(sw2);
    float bsum = 0.f;
    int n = bm + tid;
    if (tid < BM && n < N) {
        int dag = g_dagid[n];
        const float4* yz4 = reinterpret_cast<const float4*>(&g_yzop[dag * NH1]);
        float h1[NH1];
#pragma unroll
        for (int q = 0; q < 8; q++) {
            float4 v = yz4[q];
            h1[q * 4 + 0] = fmaxf(s_buf[tid * SHP + q * 4 + 0] + v.x, 0.f);
            h1[q * 4 + 1] = fmaxf(s_buf[tid * SHP + q * 4 + 1] + v.y, 0.f);
            h1[q * 4 + 2] = fmaxf(s_buf[tid * SHP + q * 4 + 2] + v.z, 0.f);
            h1[q * 4 + 3] = fmaxf(s_buf[tid * SHP + q * 4 + 3] + v.w, 0.f);
        }
        unsigned long long a2[8];
#pragma unroll
        for (int p = 0; p < 8; p++) a2[p] = pack2(sb2[2 * p], sb2[2 * p + 1]);
#pragma unroll
        for (int j = 0; j < NH1; j++) {
            unsigned long long hd = pack2(h1[j], h1[j]);
#pragma unroll
            for (int p = 0; p < 8; p++) ffma2(a2[p], hd, w2_64[j * 8 + p]);
        }
        float logit = sb3v;
#pragma unroll
        for (int p = 0; p < 8; p++) {
            float2 f = unpack2(a2[p]);
            logit += fmaxf(f.x, 0.f) * sw3[2 * p] + fmaxf(f.y, 0.f) * sw3[2 * p + 1];
        }
        logit -= (1.f - msk[n]) * 1000.f;
        float e = expf(logit);   // logits O(1); masked -> exp(-1000)=0. no max-sub needed
        out[n] = e;
        bsum = e;
    }
    // deterministic block partial sum
#pragma unroll
    for (int off = 16; off; off >>= 1) bsum += __shfl_down_sync(0xffffffffu, bsum, off);
    if (lane == 0) swr[w] = bsum;
    __syncthreads();
    if (tid == 0) {
        g_partial[blk] = ((swr[0] + swr[1]) + (swr[2] + swr[3]))
                       + ((swr[4] + swr[5]) + (swr[6] + swr[7]));
        __threadfence();
        unsigned int prev = atomicAdd(&g_counter, 1u);
        s_last = (prev == (unsigned)nb - 1) ? 1 : 0;
    }
    __syncthreads();
    if (s_last) {
        __threadfence();
        const volatile float* vp = g_partial;
        float a = 0.f;
        for (int i = tid; i < nb; i += 256) a += vp[i];
#pragma unroll
        for (int off = 16; off; off >>= 1) a += __shfl_down_sync(0xffffffffu, a, off);
        if (lane == 0) swr[w] = a;
        __syncthreads();
        if (tid == 0)
            g_inv = 1.0f / (((swr[0] + swr[1]) + (swr[2] + swr[3]))
                          + ((swr[4] + swr[5]) + (swr[6] + swr[7])));
    }
}

// ================= kernel N: normalize ops output =================
__global__ void __launch_bounds__(1024) k_norm(float* __restrict__ out, int N) {
    float inv = g_inv;
    int i4 = blockIdx.x * 1024 + threadIdx.x;
    if (i4 * 4 < N) {
        float4* o4 = reinterpret_cast<float4*>(out);
        float4 v = o4[i4];
        v.x *= inv; v.y *= inv; v.z *= inv; v.w *= inv;
        o4[i4] = v;
    }
}

// ================= launch =================
extern "C" void kernel_launch(void* const* d_in, const int* in_sizes, int n_in,
                              void* d_out, int out_size) {
    int ix = 0; long long best = -1;
    for (int i = 0; i < n_in; i++)
        if ((long long)in_sizes[i] > best) { best = in_sizes[i]; ix = i; }

    const int*   num_ops = (const int*)d_in[0];
    const float* x    = (const float*)d_in[ix];
    const float* y    = (const float*)d_in[ix + 1];
    const float* z    = (const float*)d_in[ix + 2];
    const float* omsk = (const float*)d_in[ix + 3];
    const float* pmsk = (const float*)d_in[ix + 4];
    const float* oW1  = (const float*)d_in[ix + 5];
    const float* ob1  = (const float*)d_in[ix + 6];
    const float* oW2  = (const float*)d_in[ix + 7];
    const float* ob2  = (const float*)d_in[ix + 8];
    const float* oW3  = (const float*)d_in[ix + 9];
    const float* ob3  = (const float*)d_in[ix + 10];
    const float* pW1  = (const float*)d_in[ix + 11];
    const float* pb1  = (const float*)d_in[ix + 12];
    const float* pW2  = (const float*)d_in[ix + 13];
    const float* pb2  = (const float*)d_in[ix + 14];
    const float* pW3  = (const float*)d_in[ix + 15];
    const float* pb3  = (const float*)d_in[ix + 16];

    int N = in_sizes[ix] / EMB;
    int D = in_sizes[ix + 1] / EMB;
    int W = in_sizes[ix + 4] / D;

    float* out  = (float*)d_out;
    float* outp = out + N;

    int nbF  = (N + 511) / 512;
    int nb16 = (D + 15) / 16;
    int nb   = (N + BM - 1) / BM;
    int nbPR = (D + 3) / 4;
    int nbNm = (N + 4095) / 4096;

    k_A<<<2, 1024>>>(num_ops, z, oW1, ob1, pW1, pb1, D);
    k_B<<<nbF + 2 * nb16, 512>>>(y, oW1, pW1, D, N, nbF, nb16);
    k_ops<<<nbPR + nb, 256>>>(x, oW1, oW2, ob2, oW3, ob3, omsk,
                              pW1, pW2, pb2, pW3, pb3, pmsk,
                              out, outp, N, W, D, nbPR, nb);
    k_norm<<<nbNm, 1024>>>(out, N);
}

// round 6
// speedup vs baseline: 1.0721x; 1.0721x over previous
#include <cuda_runtime.h>
#include <math.h>

#define EMB 256
#define NH1 32
#define NH2 16
#define MAXDAGS 1024
#define MAXOPS  102400

// ---------------- scratch (device globals; no allocation allowed) ----------------
__device__ int   g_offsets[MAXDAGS + 1];
__device__ int   g_dagid[MAXOPS];
__device__ float g_yzop[MAXDAGS * NH1];
__device__ float g_prpre[MAXDAGS * NH1];
__device__ float g_zop[NH1];
__device__ float g_zpr[NH1];
__device__ float g_partial[1024];
__device__ float g_inv;
__device__ unsigned int g_counter;

// ---------------- f32x2 helpers ----------------
__device__ __forceinline__ void ffma2(unsigned long long& d, unsigned long long a, unsigned long long b) {
    asm("fma.rn.f32x2 %0, %1, %2, %0;" : "+l"(d) : "l"(a), "l"(b));
}
__device__ __forceinline__ unsigned long long pack2(float x, float y) {
    unsigned long long r;
    asm("mov.b64 %0, {%1,%2};" : "=l"(r) : "f"(x), "f"(y));
    return r;
}
__device__ __forceinline__ float2 unpack2(unsigned long long v) {
    float2 r;
    asm("mov.b64 {%0,%1}, %2;" : "=f"(r.x), "=f"(r.y) : "l"(v));
    return r;
}

// ================= kernel A: block0 = prefix scan (+counter reset), block1 = z-dots =================
__global__ void __launch_bounds__(1024) k_A(
    const int* __restrict__ num_ops, const float* __restrict__ z,
    const float* __restrict__ opW1, const float* __restrict__ opb1,
    const float* __restrict__ prW1, const float* __restrict__ prb1, int D)
{
    __shared__ int s[1024];
    __shared__ float sz[EMB];
    int t = threadIdx.x;
    if (blockIdx.x == 0) {
        if (t == 0) g_counter = 0u;
        int v = (t < D) ? num_ops[t] : 0;
        s[t] = v;
        __syncthreads();
        for (int off = 1; off < 1024; off <<= 1) {
            int u = (t >= off) ? s[t - off] : 0;
            __syncthreads();
            s[t] += u;
            __syncthreads();
        }
        g_offsets[t + 1] = s[t];
        if (t == 0) g_offsets[0] = 0;
    } else {
        for (int i = t; i < EMB; i += 1024) sz[i] = z[i];
        __syncthreads();
        if (t < 64) {
            int j = t & 31;
            const float* W = (t < 32) ? (opW1 + 2 * EMB * NH1) : (prW1 + (1 + EMB) * NH1);
            float a0 = 0.f, a1 = 0.f, a2 = 0.f, a3 = 0.f;
            for (int k = 0; k < EMB; k += 4) {
                a0 += sz[k + 0] * W[(k + 0) * NH1 + j];
                a1 += sz[k + 1] * W[(k + 1) * NH1 + j];
                a2 += sz[k + 2] * W[(k + 2) * NH1 + j];
                a3 += sz[k + 3] * W[(k + 3) * NH1 + j];
            }
            float a = (a0 + a1) + (a2 + a3);
            if (t < 32) g_zop[j] = a + opb1[j];
            else        g_zpr[j] = a + prb1[j];
        }
    }
}

// ================= kernel B: blocks [0,nbF) = binary-search dag-id fill; rest = per-dag y-dots =================
__global__ void __launch_bounds__(512) k_B(
    const float* __restrict__ y,
    const float* __restrict__ opW1, const float* __restrict__ prW1,
    int D, int N, int nbF, int nb16)
{
    __shared__ float sy[16 * EMB];   // 16 KB (also aliases offsets for fill blocks)
    __shared__ float sw[64 * NH1];   // 8 KB
    int t = threadIdx.x;

    if ((int)blockIdx.x < nbF) {
        int* soff = reinterpret_cast<int*>(sy);
        for (int i = t; i <= D; i += 512) soff[i] = g_offsets[i];
        __syncthreads();
        int i = blockIdx.x * 512 + t;
        if (i < N) {
            int lo = 0, hi = D;
            while (lo < hi) {
                int mid = (lo + hi) >> 1;
                if (soff[mid + 1] <= i) lo = mid + 1; else hi = mid;
            }
            if (lo >= D) lo = D - 1;
            g_dagid[i] = lo;
        }
        return;
    }
    int bp = blockIdx.x - nbF;
    int branch = (bp >= nb16) ? 1 : 0;
    int chunk = branch ? bp - nb16 : bp;
    int w = t >> 5, j = t & 31;
    int d = chunk * 16 + w;

    for (int idx = t; idx < 16 * EMB; idx += 512) {
        int dd = chunk * 16 + (idx >> 8);
        sy[idx] = (dd < D) ? y[(size_t)dd * EMB + (idx & 255)] : 0.f;
    }
    const float* Wm = branch ? (prW1 + NH1) : (opW1 + EMB * NH1);
    float a0 = 0.f, a1 = 0.f;
    for (int kc = 0; kc < EMB; kc += 64) {
        __syncthreads();
        for (int idx = t; idx < 64 * NH1; idx += 512) sw[idx] = Wm[(size_t)kc * NH1 + idx];
        __syncthreads();
        const float* yr = sy + w * EMB + kc;
#pragma unroll
        for (int k = 0; k < 64; k += 2) {
            a0 += yr[k + 0] * sw[(k + 0) * NH1 + j];
            a1 += yr[k + 1] * sw[(k + 1) * NH1 + j];
        }
    }
    if (d < D) {
        float a = a0 + a1;
        if (!branch) g_yzop[d * NH1 + j]  = a + g_zop[j];
        else         g_prpre[d * NH1 + j] = a + g_zpr[j];
    }
}

// ================= kernel C (fused): blocks [0,nb) = main GEMM; blocks [nb,nb+nbPR) = prlvl =================
#define BM 128
#define KC 64
#define SXP 66    // x tile row stride (floats, even for LDS.64 / STS.64)
#define SHP 34    // h-pre row stride

__global__ void __launch_bounds__(256, 2) k_ops(
    const float* __restrict__ x,  const float* __restrict__ W1,
    const float* __restrict__ W2, const float* __restrict__ b2,
    const float* __restrict__ W3, const float* __restrict__ b3,
    const float* __restrict__ msk,
    const float* __restrict__ prW1, const float* __restrict__ prW2,
    const float* __restrict__ prb2, const float* __restrict__ prW3,
    const float* __restrict__ prb3, const float* __restrict__ pmsk,
    float* __restrict__ out, float* __restrict__ outp,
    int N, int W, int D, int nbPR, int nb)
{
    // phase1: x tile row-major [BM][SXP] (33.8 KB); phase2 alias: h-pre [BM][SHP]
    __shared__ float s_buf[BM * SXP];
    __shared__ float swi[(KC / 2) * 64];   // interleaved W1 chunk: [kp][2j+e]  (8 KB)
    __shared__ float sw2[NH1 * NH2];
    __shared__ float sb2[NH2], sw3[NH2];
    __shared__ float sb3v;
    __shared__ float swr[8];
    __shared__ int   s_last;

    int tid  = threadIdx.x;
    int w    = tid >> 5;
    int lane = tid & 31;

    // ---------------- prlvl path: 4 dags per block (tail blocks) ----------------
    if ((int)blockIdx.x >= nb) {
        float* spre = s_buf;               // 128 floats
        float* sr0  = s_buf + 128;         // 32
        float* sW2p = sw2;
        int dbase = (blockIdx.x - nb) * 4;
        int dl = tid >> 6, wk = tid & 63;
        int d = dbase + dl;

        if (tid < 4 * NH1) {
            int dd = dbase + (tid >> 5);
            spre[tid] = (dd < D) ? g_prpre[dbase * NH1 + tid] : 0.f;
        }
        if (tid >= 128 && tid < 160) sr0[tid - 128] = prW1[tid - 128];
        for (int i = tid; i < NH1 * NH2; i += 256) sW2p[i] = prW2[i];
        if (tid >= 160 && tid < 176) { sb2[tid - 160] = prb2[tid - 160]; sw3[tid - 160] = prW3[tid - 160]; }
        if (tid == 176) sb3v = prb3[0];
        __syncthreads();

        const unsigned long long* w2p = reinterpret_cast<const unsigned long long*>(sW2p);
        float l = -1e30f;
        if (d < D && wk < W) {
            float lim = (float)(wk + 1);
            float h1[NH1];
#pragma unroll
            for (int j = 0; j < NH1; j++) h1[j] = fmaxf(spre[dl * NH1 + j] + lim * sr0[j], 0.f);
            unsigned long long a2[8];
#pragma unroll
            for (int p = 0; p < 8; p++) a2[p] = pack2(sb2[2 * p], sb2[2 * p + 1]);
#pragma unroll
            for (int j = 0; j < NH1; j++) {
                unsigned long long hd = pack2(h1[j], h1[j]);
#pragma unroll
                for (int p = 0; p < 8; p++) ffma2(a2[p], hd, w2p[j * 8 + p]);
            }
            float logit = sb3v;
#pragma unroll
            for (int p = 0; p < 8; p++) {
                float2 f = unpack2(a2[p]);
                logit += fmaxf(f.x, 0.f) * sw3[2 * p] + fmaxf(f.y, 0.f) * sw3[2 * p + 1];
            }
            l = logit - (1.f - pmsk[(size_t)d * W + wk]) * 1000.f;
        }
        float m = l;
#pragma unroll
        for (int off = 16; off; off >>= 1) m = fmaxf(m, __shfl_xor_sync(0xffffffffu, m, off));
        if (lane == 0) swr[w] = m;
        __syncthreads();
        m = fmaxf(swr[dl * 2], swr[dl * 2 + 1]);
        float e = (d < D && wk < W) ? expf(l - m) : 0.f;
        float s = e;
#pragma unroll
        for (int off = 16; off; off >>= 1) s += __shfl_xor_sync(0xffffffffu, s, off);
        __syncthreads();
        if (lane == 0) swr[w] = s;
        __syncthreads();
        s = swr[dl * 2] + swr[dl * 2 + 1];
        if (d < D && wk < W) outp[(size_t)d * W + wk] = e / s;
        return;
    }

    // ---------------- GEMM path ----------------
    int blk  = blockIdx.x;
    int bm   = blk * BM;
    int j0   = (w & 3) * 8;              // warp -> 8 j's (broadcast within warp)
    int rh   = (w >> 2) * 64;            // row half

    if (tid < 16) { sb2[tid] = b2[tid]; sw3[tid] = W3[tid]; }
    if (tid == 16) sb3v = b3[0];
    for (int i = tid; i < NH1 * NH2; i += 256) sw2[i] = W2[i];

    unsigned long long acc[2][8];
#pragma unroll
    for (int i = 0; i < 2; i++)
#pragma unroll
        for (int p = 0; p < 8; p++) acc[i][p] = 0ull;

    for (int kc = 0; kc < EMB; kc += KC) {
        __syncthreads();
        // stage x tile row-major via float2 (coalesced LDG.64, aligned STS.64)
#pragma unroll
        for (int it = 0; it < 16; it++) {
            int fi = it * 256 + tid;
            int row = fi >> 5, c2 = fi & 31;
            int n = bm + row;
            float2 v = make_float2(0.f, 0.f);
            if (n < N) v = *reinterpret_cast<const float2*>(&x[(size_t)n * EMB + kc + c2 * 2]);
            *reinterpret_cast<float2*>(&s_buf[row * SXP + c2 * 2]) = v;
        }
        // stage W1 chunk interleaved: swi[kp*64 + r] = W1[(kc+2kp+(r&1))*32 + (r>>1)]
#pragma unroll
        for (int it = 0; it < 8; it++) {
            int idx = it * 256 + tid;            // 0..2047
            int kp = idx >> 6, r = idx & 63;
            swi[kp * 64 + r] = W1[(size_t)(kc + 2 * kp + (r & 1)) * NH1 + (r >> 1)];
        }
        __syncthreads();
#pragma unroll 4
        for (int kp = 0; kp < KC / 2; kp++) {
            unsigned long long xk0 = *reinterpret_cast<const unsigned long long*>(
                &s_buf[(rh + lane) * SXP + 2 * kp]);
            unsigned long long xk1 = *reinterpret_cast<const unsigned long long*>(
                &s_buf[(rh + lane + 32) * SXP + 2 * kp]);
            const ulonglong2* wp = reinterpret_cast<const ulonglong2*>(&swi[kp * 64 + 2 * j0]);
            ulonglong2 wa = wp[0], wb = wp[1], wc = wp[2], wd = wp[3];
            ffma2(acc[0][0], xk0, wa.x); ffma2(acc[0][1], xk0, wa.y);
            ffma2(acc[0][2], xk0, wb.x); ffma2(acc[0][3], xk0, wb.y);
            ffma2(acc[0][4], xk0, wc.x); ffma2(acc[0][5], xk0, wc.y);
            ffma2(acc[0][6], xk0, wd.x); ffma2(acc[0][7], xk0, wd.y);
            ffma2(acc[1][0], xk1, wa.x); ffma2(acc[1][1], xk1, wa.y);
            ffma2(acc[1][2], xk1, wb.x); ffma2(acc[1][3], xk1, wb.y);
            ffma2(acc[1][4], xk1, wc.x); ffma2(acc[1][5], xk1, wc.y);
            ffma2(acc[1][6], xk1, wd.x); ffma2(acc[1][7], xk1, wd.y);
        }
    }
    __syncthreads();
    // reduce lanes (even+odd k) and stage h-pre
#pragma unroll
    for (int i = 0; i < 2; i++) {
        int row = rh + lane + 32 * i;
#pragma unroll
        for (int p = 0; p < 8; p++) {
            float2 f = unpack2(acc[i][p]);
            s_buf[row * SHP + j0 + p] = f.x + f.y;
        }
    }
    __syncthreads();

    // ---- tail: rows 0..127 handled by tid<128 ----
    const unsigned long long* w2_64 = reinterpret_cast<const unsigned long long*>(sw2);
    float bsum = 0.f;
    int n = bm + tid;
    if (tid < BM && n < N) {
        int dag = g_dagid[n];
        const float4* yz4 = reinterpret_cast<const float4*>(&g_yzop[dag * NH1]);
        float h1[NH1];
#pragma unroll
        for (int q = 0; q < 8; q++) {
            float4 v = yz4[q];
            h1[q * 4 + 0] = fmaxf(s_buf[tid * SHP + q * 4 + 0] + v.x, 0.f);
            h1[q * 4 + 1] = fmaxf(s_buf[tid * SHP + q * 4 + 1] + v.y, 0.f);
            h1[q * 4 + 2] = fmaxf(s_buf[tid * SHP + q * 4 + 2] + v.z, 0.f);
            h1[q * 4 + 3] = fmaxf(s_buf[tid * SHP + q * 4 + 3] + v.w, 0.f);
        }
        unsigned long long a2[8];
#pragma unroll
        for (int p = 0; p < 8; p++) a2[p] = pack2(sb2[2 * p], sb2[2 * p + 1]);
#pragma unroll
        for (int j = 0; j < NH1; j++) {
            unsigned long long hd = pack2(h1[j], h1[j]);
#pragma unroll
            for (int p = 0; p < 8; p++) ffma2(a2[p], hd, w2_64[j * 8 + p]);
        }
        float logit = sb3v;
#pragma unroll
        for (int p = 0; p < 8; p++) {
            float2 f = unpack2(a2[p]);
            logit += fmaxf(f.x, 0.f) * sw3[2 * p] + fmaxf(f.y, 0.f) * sw3[2 * p + 1];
        }
        logit -= (1.f - msk[n]) * 1000.f;
        float e = expf(logit);   // logits O(1); masked -> exp(-1000)=0. no max-sub needed
        out[n] = e;
        bsum = e;
    }
    // deterministic block partial sum
#pragma unroll
    for (int off = 16; off; off >>= 1) bsum += __shfl_down_sync(0xffffffffu, bsum, off);
    if (lane == 0) swr[w] = bsum;
    __syncthreads();
    if (tid == 0) {
        g_partial[blk] = ((swr[0] + swr[1]) + (swr[2] + swr[3]))
                       + ((swr[4] + swr[5]) + (swr[6] + swr[7]));
        __threadfence();
        unsigned int prev = atomicAdd(&g_counter, 1u);
        s_last = (prev == (unsigned)nb - 1) ? 1 : 0;
    }
    __syncthreads();
    if (s_last) {
        __threadfence();
        const volatile float* vp = g_partial;
        float a = 0.f;
        for (int i = tid; i < nb; i += 256) a += vp[i];
#pragma unroll
        for (int off = 16; off; off >>= 1) a += __shfl_down_sync(0xffffffffu, a, off);
        if (lane == 0) swr[w] = a;
        __syncthreads();
        if (tid == 0)
            g_inv = 1.0f / (((swr[0] + swr[1]) + (swr[2] + swr[3]))
                          + ((swr[4] + swr[5]) + (swr[6] + swr[7])));
    }
}

// ================= kernel N: normalize ops output =================
__global__ void __launch_bounds__(128) k_norm(float* __restrict__ out, int N) {
    float inv = g_inv;
    int i4 = blockIdx.x * 128 + threadIdx.x;
    if (i4 * 4 < N) {
        float4* o4 = reinterpret_cast<float4*>(out);
        float4 v = o4[i4];
        v.x *= inv; v.y *= inv; v.z *= inv; v.w *= inv;
        o4[i4] = v;
    }
}

// ================= launch =================
extern "C" void kernel_launch(void* const* d_in, const int* in_sizes, int n_in,
                              void* d_out, int out_size) {
    int ix = 0; long long best = -1;
    for (int i = 0; i < n_in; i++)
        if ((long long)in_sizes[i] > best) { best = in_sizes[i]; ix = i; }

    const int*   num_ops = (const int*)d_in[0];
    const float* x    = (const float*)d_in[ix];
    const float* y    = (const float*)d_in[ix + 1];
    const float* z    = (const float*)d_in[ix + 2];
    const float* omsk = (const float*)d_in[ix + 3];
    const float* pmsk = (const float*)d_in[ix + 4];
    const float* oW1  = (const float*)d_in[ix + 5];
    const float* ob1  = (const float*)d_in[ix + 6];
    const float* oW2  = (const float*)d_in[ix + 7];
    const float* ob2  = (const float*)d_in[ix + 8];
    const float* oW3  = (const float*)d_in[ix + 9];
    const float* ob3  = (const float*)d_in[ix + 10];
    const float* pW1  = (const float*)d_in[ix + 11];
    const float* pb1  = (const float*)d_in[ix + 12];
    const float* pW2  = (const float*)d_in[ix + 13];
    const float* pb2  = (const float*)d_in[ix + 14];
    const float* pW3  = (const float*)d_in[ix + 15];
    const float* pb3  = (const float*)d_in[ix + 16];

    int N = in_sizes[ix] / EMB;
    int D = in_sizes[ix + 1] / EMB;
    int W = in_sizes[ix + 4] / D;

    float* out  = (float*)d_out;
    float* outp = out + N;

    int nbF  = (N + 511) / 512;
    int nb16 = (D + 15) / 16;
    int nb   = (N + BM - 1) / BM;
    int nbPR = (D + 3) / 4;
    int nbNm = (N / 4 + 127) / 128;

    k_A<<<2, 1024>>>(num_ops, z, oW1, ob1, pW1, pb1, D);
    k_B<<<nbF + 2 * nb16, 512>>>(y, oW1, pW1, D, N, nbF, nb16);
    k_ops<<<nb + nbPR, 256>>>(x, oW1, oW2, ob2, oW3, ob3, omsk,
                              pW1, pW2, pb2, pW3, pb3, pmsk,
                              out, outp, N, W, D, nbPR, nb);
    k_norm<<<nbNm, 128>>>(out, N);
}